// round 14
// baseline (speedup 1.0000x reference)
#include <cuda_runtime.h>
#include <cuda_fp16.h>
#include <stdint.h>

typedef unsigned int u32;
typedef unsigned long long u64;

#define D_C   1024
#define N_T   2048
#define M_TOT 16384   // 8 * 2048
#define NCH   8192    // B * D_C chains
#define SCH   32      // scan chunks
#define LCH   64      // tokens per chunk (SCH*LCH = N_T)

// ---------------- scratch (__device__ globals; no cudaMalloc allowed) ---------
__device__ __half g_xk[(size_t)M_TOT * D_C];
__device__ __half g_xv[(size_t)M_TOT * D_C];
__device__ __half g_xr[(size_t)M_TOT * D_C];
__device__ __half g_rw[(size_t)M_TOT * D_C];
__device__ __half g_k [(size_t)M_TOT * D_C];
__device__ __half g_v [(size_t)M_TOT * D_C];
__device__ __half g_r [(size_t)M_TOT * D_C];
__device__ __half g_wk[(size_t)D_C * D_C];
__device__ __half g_wv[(size_t)D_C * D_C];
__device__ __half g_wr[(size_t)D_C * D_C];
__device__ __half g_wo[(size_t)D_C * D_C];
// chunked-scan state: [SCH][NCH]
__device__ float g_saa[SCH * NCH], g_sbb[SCH * NCH], g_spp[SCH * NCH];
__device__ float g_iaa[SCH * NCH], g_ibb[SCH * NCH], g_ipp[SCH * NCH];

// ---------------- PTX helpers (baseline ISA only) ------------------------------
__device__ __forceinline__ u32 smem_u32(const void* p) {
    u32 a;
    asm("{ .reg .u64 t; cvta.to.shared.u64 t, %1; cvt.u32.u64 %0, t; }"
        : "=r"(a) : "l"(p));
    return a;
}
#define SWZ(o) ((u32)(o) ^ ((((u32)(o)) >> 3) & 0x70))

__device__ __forceinline__ void cpasync16(u32 s, const void* g) {
    asm volatile("cp.async.cg.shared.global [%0], [%1], 16;" :: "r"(s), "l"(g));
}
#define CP_COMMIT asm volatile("cp.async.commit_group;" ::: "memory")
#define CP_WAIT1  asm volatile("cp.async.wait_group 1;" ::: "memory")
#define CP_WAIT0  asm volatile("cp.async.wait_group 0;" ::: "memory")

__device__ __forceinline__ void ldsm4(u32& r0, u32& r1, u32& r2, u32& r3, u32 a) {
    asm volatile("ldmatrix.sync.aligned.m8n8.x4.shared.b16 {%0,%1,%2,%3}, [%4];"
                 : "=r"(r0), "=r"(r1), "=r"(r2), "=r"(r3) : "r"(a));
}

__device__ __forceinline__ void mma_f16(float* d, u32 a0, u32 a1, u32 a2, u32 a3,
                                        u32 b0, u32 b1) {
    asm volatile(
        "mma.sync.aligned.m16n8k16.row.col.f32.f16.f16.f32 "
        "{%0,%1,%2,%3},{%4,%5,%6,%7},{%8,%9},{%0,%1,%2,%3};"
        : "+f"(d[0]), "+f"(d[1]), "+f"(d[2]), "+f"(d[3])
        : "r"(a0), "r"(a1), "r"(a2), "r"(a3), "r"(b0), "r"(b1));
}

__device__ __forceinline__ u32 pack_h2(float lo, float hi) {
    __half2 h = __floats2half2_rn(lo, hi);
    return *(u32*)&h;
}

// epilogue store: fp32 or fp16 output, same call site
__device__ __forceinline__ void st2(float* C, size_t idx, float a, float b) {
    *(float2*)&C[idx] = make_float2(a, b);
}
__device__ __forceinline__ void st2(__half* C, size_t idx, float a, float b) {
    *(__half2*)&C[idx] = __floats2half2_rn(a, b);
}

// ---------------- weight convert: 4 matrices fp32 -> fp16, one launch ---------
__global__ void wconv_kernel(const float4* __restrict__ W0, __half* __restrict__ O0,
                             const float4* __restrict__ W1, __half* __restrict__ O1,
                             const float4* __restrict__ W2, __half* __restrict__ O2,
                             const float4* __restrict__ W3, __half* __restrict__ O3) {
    int i = blockIdx.x * blockDim.x + threadIdx.x;
    const float4* W = (blockIdx.y == 0) ? W0 : (blockIdx.y == 1) ? W1
                    : (blockIdx.y == 2) ? W2 : W3;
    __half* O = (blockIdx.y == 0) ? O0 : (blockIdx.y == 1) ? O1
              : (blockIdx.y == 2) ? O2 : O3;
    float4 v = W[i];
    ((uint2*)O)[i] = make_uint2(pack_h2(v.x, v.y), pack_h2(v.z, v.w));
}

// ---------------- token-shift mix -> fp16 -------------------------------------
__global__ void mix_kernel(const float* __restrict__ x,
                           const float* __restrict__ tmk,
                           const float* __restrict__ tmv,
                           const float* __restrict__ tmr) {
    const int C4 = D_C / 4;
    int i = blockIdx.x * blockDim.x + threadIdx.x;
    int c4 = i & (C4 - 1);
    int bt = i >> 8;
    int t  = bt & (N_T - 1);

    float4 xc = ((const float4*)x)[i];
    float4 xs = make_float4(0.f, 0.f, 0.f, 0.f);
    if (t > 0) xs = ((const float4*)x)[i - C4];

    float4 mk = ((const float4*)tmk)[c4];
    float4 mv = ((const float4*)tmv)[c4];
    float4 mr = ((const float4*)tmr)[c4];

    float kx = xc.x * mk.x + xs.x * (1.f - mk.x);
    float ky = xc.y * mk.y + xs.y * (1.f - mk.y);
    float kz = xc.z * mk.z + xs.z * (1.f - mk.z);
    float kw = xc.w * mk.w + xs.w * (1.f - mk.w);
    float vx = xc.x * mv.x + xs.x * (1.f - mv.x);
    float vy = xc.y * mv.y + xs.y * (1.f - mv.y);
    float vz = xc.z * mv.z + xs.z * (1.f - mv.z);
    float vw = xc.w * mv.w + xs.w * (1.f - mv.w);
    float rx = xc.x * mr.x + xs.x * (1.f - mr.x);
    float ry = xc.y * mr.y + xs.y * (1.f - mr.y);
    float rz = xc.z * mr.z + xs.z * (1.f - mr.z);
    float rw = xc.w * mr.w + xs.w * (1.f - mr.w);

    ((uint2*)g_xk)[i] = make_uint2(pack_h2(kx, ky), pack_h2(kz, kw));
    ((uint2*)g_xv)[i] = make_uint2(pack_h2(vx, vy), pack_h2(vz, vw));
    ((uint2*)g_xr)[i] = make_uint2(pack_h2(rx, ry), pack_h2(rz, rw));
}

// ---------------- fp16 mma.sync GEMM (256x256 tile, 512 threads) ---------------
// C[m,n] = sum_k A[m,k]*W[n,k]; fp16 in, OT out. CTA 256x256, BK=64,
// 3-stage cp.async, one __syncthreads per k-iter. 16 warps of 64x64.
// blockIdx.z picks matrix set.
#define GBM 256
#define GBN 256
#define STG 65536                 // per-stage bytes: A 32K + B 32K
#define GSMEM (3 * STG)           // 192 KB

template <typename OT>
__global__ __launch_bounds__(512, 1)
void gemm_f16(const __half* __restrict__ A0, const __half* __restrict__ W0,
              OT* __restrict__ C0,
              const __half* __restrict__ A1, const __half* __restrict__ W1,
              OT* __restrict__ C1,
              const __half* __restrict__ A2, const __half* __restrict__ W2,
              OT* __restrict__ C2) {
    extern __shared__ char smem[];
    u32 sb = smem_u32(smem);
    const int tid = threadIdx.x, lane = tid & 31, wid = tid >> 5;
    const int bm = blockIdx.y * GBM, bn = blockIdx.x * GBN;
    const int mband = (wid >> 2) * 64, nband = (wid & 3) * 64;

    const __half* A = (blockIdx.z == 0) ? A0 : (blockIdx.z == 1) ? A1 : A2;
    const __half* W = (blockIdx.z == 0) ? W0 : (blockIdx.z == 1) ? W1 : W2;
    OT*           C = (blockIdx.z == 0) ? C0 : (blockIdx.z == 1) ? C1 : C2;

    const int arow = lane & 15;
    const int acg  = (lane >> 4) * 16;
    const int brow = ((lane >> 4) & 1) * 8 + (lane & 7);
    const int bcg  = ((lane >> 3) & 1) * 16;

    float acc[4][8][4];
#pragma unroll
    for (int i = 0; i < 4; i++)
#pragma unroll
        for (int j = 0; j < 8; j++)
#pragma unroll
            for (int q = 0; q < 4; q++) acc[i][j][q] = 0.f;

    const __half* Ag = A + (size_t)bm * D_C;
    const __half* Wg = W + (size_t)bn * D_C;

    // stage kt -> smem buffer (kt%3): A 256x64h at +0, W 256x64h at +32768
#define ISSUE(kt)                                                              \
    {                                                                          \
        u32 st = sb + ((kt) % 3) * STG;                                        \
        int koff = (kt) * 64;                                                  \
        _Pragma("unroll")                                                      \
        for (int ii = 0; ii < 4; ii++) {                                       \
            int g = tid + (ii << 9);                                           \
            int row = g >> 3, c8 = g & 7;                                      \
            u32 so = SWZ(row * 128 + c8 * 16);                                 \
            cpasync16(st + so,         Ag + (size_t)row * D_C + koff + c8 * 8);\
            cpasync16(st + 32768 + so, Wg + (size_t)row * D_C + koff + c8 * 8);\
        }                                                                      \
        CP_COMMIT;                                                             \
    }

    ISSUE(0); ISSUE(1);
    for (int kt = 0; kt < 16; kt++) {
        if (kt == 15) { CP_WAIT0; } else { CP_WAIT1; }
        __syncthreads();
        if (kt + 2 < 16) ISSUE(kt + 2);

        u32 aB = sb + (kt % 3) * STG;
        u32 bB = aB + 32768;
#pragma unroll
        for (int s = 0; s < 4; s++) {
            u32 af[4][4];
#pragma unroll
            for (int i = 0; i < 4; i++) {
                u32 addr = aB + SWZ((mband + 16 * i + arow) * 128 + s * 32 + acg);
                ldsm4(af[i][0], af[i][1], af[i][2], af[i][3], addr);
            }
#pragma unroll
            for (int jp = 0; jp < 4; jp++) {
                u32 b0, b1, b2, b3;
                u32 addr = bB + SWZ((nband + 16 * jp + brow) * 128 + s * 32 + bcg);
                ldsm4(b0, b1, b2, b3, addr);
#pragma unroll
                for (int i = 0; i < 4; i++) {
                    mma_f16(acc[i][2 * jp],     af[i][0], af[i][1], af[i][2], af[i][3], b0, b1);
                    mma_f16(acc[i][2 * jp + 1], af[i][0], af[i][1], af[i][2], af[i][3], b2, b3);
                }
            }
        }
    }

#pragma unroll
    for (int i = 0; i < 4; i++) {
        int row = bm + mband + 16 * i + (lane >> 2);
#pragma unroll
        for (int j = 0; j < 8; j++) {
            int col = bn + nband + 8 * j + 2 * (lane & 3);
            st2(C, (size_t)row * D_C + col,       acc[i][j][0], acc[i][j][1]);
            st2(C, (size_t)(row + 8) * D_C + col, acc[i][j][2], acc[i][j][3]);
        }
    }
}

// ---------------- WKV chunked scan (fp16 k/v/r IO) ----------------------------
// pass1: per (chain, chunk) compute chunk-local state from zero init.
__global__ void wkv_pass1(const float* __restrict__ w) {
    int g = blockIdx.x * blockDim.x + threadIdx.x;  // 0..SCH*NCH-1
    int chain = g & (NCH - 1), s = g >> 13;
    int b = chain >> 10, c = chain & (D_C - 1);
    float wn = -__expf(w[c]);

    size_t base = (size_t)b * N_T * D_C + (size_t)s * LCH * D_C + c;
    const __half* kp = g_k + base;
    const __half* vp = g_v + base;

    float aa = 0.f, bb = 0.f, pp = -1e38f;
#pragma unroll 8
    for (int j = 0; j < LCH; j++) {
        float kt = __half2float(kp[(size_t)j * D_C]);
        float vt = __half2float(vp[(size_t)j * D_C]);
        float ww2 = pp + wn;
        float p2  = fmaxf(ww2, kt);
        float e1b = __expf(ww2 - p2);
        float e2b = __expf(kt - p2);
        aa = e1b * aa + e2b * vt;
        bb = e1b * bb + e2b;
        pp = p2;
    }
    int o = s * NCH + chain;
    g_saa[o] = aa; g_sbb[o] = bb; g_spp[o] = pp;
}

// pass2: sequential merge over chunks; store incoming state per chunk.
__global__ void wkv_pass2(const float* __restrict__ w) {
    int chain = blockIdx.x * blockDim.x + threadIdx.x;  // 0..NCH-1
    int c = chain & (D_C - 1);
    float wn = -__expf(w[c]);
    float Lwn = (float)LCH * wn;

    float aa = 0.f, bb = 0.f, pp = -1e38f;
#pragma unroll
    for (int s = 0; s < SCH; s++) {
        int o = s * NCH + chain;
        g_iaa[o] = aa; g_ibb[o] = bb; g_ipp[o] = pp;
        float la = g_saa[o], lb = g_sbb[o], lp = g_spp[o];
        float ppa = pp + Lwn;
        float ppm = fmaxf(ppa, lp);
        float e1 = __expf(ppa - ppm);
        float e2 = __expf(lp - ppm);
        aa = e1 * aa + e2 * la;
        bb = e1 * bb + e2 * lb;
        pp = ppm;
    }
}

// pass3: replay each chunk from incoming state, produce gated outputs.
__global__ void wkv_pass3(const float* __restrict__ w,
                          const float* __restrict__ u) {
    int g = blockIdx.x * blockDim.x + threadIdx.x;
    int chain = g & (NCH - 1), s = g >> 13;
    int b = chain >> 10, c = chain & (D_C - 1);
    float wn = -__expf(w[c]);
    float uc = u[c];

    int o = s * NCH + chain;
    float aa = g_iaa[o], bb = g_ibb[o], pp = g_ipp[o];

    size_t base = (size_t)b * N_T * D_C + (size_t)s * LCH * D_C + c;
    const __half* kp = g_k + base;
    const __half* vp = g_v + base;
    const __half* rp = g_r + base;
    __half*       op = g_rw + base;

#pragma unroll 8
    for (int j = 0; j < LCH; j++) {
        float kt = __half2float(kp[(size_t)j * D_C]);
        float vt = __half2float(vp[(size_t)j * D_C]);
        float rt = __half2float(rp[(size_t)j * D_C]);

        float ww = uc + kt;
        float p  = fmaxf(pp, ww);
        float e1 = __expf(pp - p);
        float e2 = __expf(ww - p);
        float y  = __fdividef(e1 * aa + e2 * vt, e1 * bb + e2);

        float sg = __fdividef(1.f, 1.f + __expf(-rt));
        op[(size_t)j * D_C] = __float2half_rn(y * sg);

        float ww2 = pp + wn;
        float p2  = fmaxf(ww2, kt);
        float e1b = __expf(ww2 - p2);
        float e2b = __expf(kt - p2);
        aa = e1b * aa + e2b * vt;
        bb = e1b * bb + e2b;
        pp = p2;
    }
}

// ---------------- launch (single stream — graph-capture safe) -----------------
extern "C" void kernel_launch(void* const* d_in, const int* in_sizes, int n_in,
                              void* d_out, int out_size) {
    const float* x   = (const float*)d_in[0];
    const float* w   = (const float*)d_in[1];
    const float* u   = (const float*)d_in[2];
    const float* tmk = (const float*)d_in[3];
    const float* tmv = (const float*)d_in[4];
    const float* tmr = (const float*)d_in[5];
    const float* Wk  = (const float*)d_in[6];
    const float* Wv  = (const float*)d_in[7];
    const float* Wr  = (const float*)d_in[8];
    const float* Wo  = (const float*)d_in[9];
    float* out = (float*)d_out;

    __half *xk, *xv, *xr, *rw, *wk, *wv, *wr, *wo, *k, *v, *r;
    cudaGetSymbolAddress((void**)&xk, g_xk);
    cudaGetSymbolAddress((void**)&xv, g_xv);
    cudaGetSymbolAddress((void**)&xr, g_xr);
    cudaGetSymbolAddress((void**)&rw, g_rw);
    cudaGetSymbolAddress((void**)&wk, g_wk);
    cudaGetSymbolAddress((void**)&wv, g_wv);
    cudaGetSymbolAddress((void**)&wr, g_wr);
    cudaGetSymbolAddress((void**)&wo, g_wo);
    cudaGetSymbolAddress((void**)&k,  g_k);
    cudaGetSymbolAddress((void**)&v,  g_v);
    cudaGetSymbolAddress((void**)&r,  g_r);

    cudaFuncSetAttribute(gemm_f16<__half>,
                         cudaFuncAttributeMaxDynamicSharedMemorySize, GSMEM);
    cudaFuncSetAttribute(gemm_f16<float>,
                         cudaFuncAttributeMaxDynamicSharedMemorySize, GSMEM);

    // 1) fp16 weights + mixed activations
    wconv_kernel<<<dim3(1024, 4), 256>>>((const float4*)Wk, wk,
                                         (const float4*)Wv, wv,
                                         (const float4*)Wr, wr,
                                         (const float4*)Wo, wo);
    mix_kernel<<<(M_TOT * D_C / 4) / 256, 256>>>(x, tmk, tmv, tmr);

    // 2) K/V/R projections in ONE z-batched launch (fp16 out)
    dim3 gg3(D_C / GBN, M_TOT / GBM, 3);   // (4, 64, 3)
    gemm_f16<__half><<<gg3, 512, GSMEM>>>(xk, wk, k, xv, wv, v, xr, wr, r);

    // 3) WKV chunked scan (parallel over SCH chunks) + sigmoid gate
    wkv_pass1<<<(SCH * NCH) / 256, 256>>>(w);
    wkv_pass2<<<NCH / 256, 256>>>(w);
    wkv_pass3<<<(SCH * NCH) / 256, 256>>>(w, u);

    // 4) output projection (fp32 out to d_out)
    dim3 gg1(D_C / GBN, M_TOT / GBM, 1);   // (4, 64, 1)
    gemm_f16<float><<<gg1, 512, GSMEM>>>(rw, wo, out, rw, wo, out, rw, wo, out);
}

// round 15
// speedup vs baseline: 2.8702x; 2.8702x over previous
#include <cuda_runtime.h>
#include <cuda_fp16.h>
#include <stdint.h>

typedef unsigned int u32;
typedef unsigned long long u64;

#define D_C   1024
#define N_T   2048
#define M_TOT 16384   // 8 * 2048
#define NCH   8192    // B * D_C chains
#define SCH   32      // scan chunks
#define LCH   64      // tokens per chunk (SCH*LCH = N_T)

// ---------------- scratch (__device__ globals; no cudaMalloc allowed) ---------
__device__ __half g_xk[(size_t)M_TOT * D_C];
__device__ __half g_xv[(size_t)M_TOT * D_C];
__device__ __half g_xr[(size_t)M_TOT * D_C];
__device__ __half g_rw[(size_t)M_TOT * D_C];
__device__ __half g_k [(size_t)M_TOT * D_C];
__device__ __half g_v [(size_t)M_TOT * D_C];
__device__ __half g_r [(size_t)M_TOT * D_C];
__device__ __half g_wk[(size_t)D_C * D_C];
__device__ __half g_wv[(size_t)D_C * D_C];
__device__ __half g_wr[(size_t)D_C * D_C];
__device__ __half g_wo[(size_t)D_C * D_C];
// chunked-scan state: [SCH][NCH]
__device__ float g_saa[SCH * NCH], g_sbb[SCH * NCH], g_spp[SCH * NCH];
__device__ float g_iaa[SCH * NCH], g_ibb[SCH * NCH], g_ipp[SCH * NCH];

// ---------------- PTX helpers (baseline ISA only) ------------------------------
__device__ __forceinline__ u32 smem_u32(const void* p) {
    u32 a;
    asm("{ .reg .u64 t; cvta.to.shared.u64 t, %1; cvt.u32.u64 %0, t; }"
        : "=r"(a) : "l"(p));
    return a;
}
#define SWZ(o) ((u32)(o) ^ ((((u32)(o)) >> 3) & 0x70))

__device__ __forceinline__ void cpasync16(u32 s, const void* g) {
    asm volatile("cp.async.cg.shared.global [%0], [%1], 16;" :: "r"(s), "l"(g));
}
#define CP_COMMIT asm volatile("cp.async.commit_group;" ::: "memory")
#define CP_WAIT2  asm volatile("cp.async.wait_group 2;" ::: "memory")
#define CP_WAIT1  asm volatile("cp.async.wait_group 1;" ::: "memory")
#define CP_WAIT0  asm volatile("cp.async.wait_group 0;" ::: "memory")

__device__ __forceinline__ void ldsm4(u32& r0, u32& r1, u32& r2, u32& r3, u32 a) {
    asm volatile("ldmatrix.sync.aligned.m8n8.x4.shared.b16 {%0,%1,%2,%3}, [%4];"
                 : "=r"(r0), "=r"(r1), "=r"(r2), "=r"(r3) : "r"(a));
}

__device__ __forceinline__ void mma_f16(float* d, u32 a0, u32 a1, u32 a2, u32 a3,
                                        u32 b0, u32 b1) {
    asm volatile(
        "mma.sync.aligned.m16n8k16.row.col.f32.f16.f16.f32 "
        "{%0,%1,%2,%3},{%4,%5,%6,%7},{%8,%9},{%0,%1,%2,%3};"
        : "+f"(d[0]), "+f"(d[1]), "+f"(d[2]), "+f"(d[3])
        : "r"(a0), "r"(a1), "r"(a2), "r"(a3), "r"(b0), "r"(b1));
}

__device__ __forceinline__ u32 pack_h2(float lo, float hi) {
    __half2 h = __floats2half2_rn(lo, hi);
    return *(u32*)&h;
}

// epilogue store: fp32 or fp16 output, same call site
__device__ __forceinline__ void st2(float* C, size_t idx, float a, float b) {
    *(float2*)&C[idx] = make_float2(a, b);
}
__device__ __forceinline__ void st2(__half* C, size_t idx, float a, float b) {
    *(__half2*)&C[idx] = __floats2half2_rn(a, b);
}

// ---------------- weight convert: 4 matrices fp32 -> fp16, one launch ---------
__global__ void wconv_kernel(const float4* __restrict__ W0, __half* __restrict__ O0,
                             const float4* __restrict__ W1, __half* __restrict__ O1,
                             const float4* __restrict__ W2, __half* __restrict__ O2,
                             const float4* __restrict__ W3, __half* __restrict__ O3) {
    int i = blockIdx.x * blockDim.x + threadIdx.x;
    const float4* W = (blockIdx.y == 0) ? W0 : (blockIdx.y == 1) ? W1
                    : (blockIdx.y == 2) ? W2 : W3;
    __half* O = (blockIdx.y == 0) ? O0 : (blockIdx.y == 1) ? O1
              : (blockIdx.y == 2) ? O2 : O3;
    float4 v = W[i];
    ((uint2*)O)[i] = make_uint2(pack_h2(v.x, v.y), pack_h2(v.z, v.w));
}

// ---------------- token-shift mix -> fp16 -------------------------------------
__global__ void mix_kernel(const float* __restrict__ x,
                           const float* __restrict__ tmk,
                           const float* __restrict__ tmv,
                           const float* __restrict__ tmr) {
    const int C4 = D_C / 4;
    int i = blockIdx.x * blockDim.x + threadIdx.x;
    int c4 = i & (C4 - 1);
    int bt = i >> 8;
    int t  = bt & (N_T - 1);

    float4 xc = ((const float4*)x)[i];
    float4 xs = make_float4(0.f, 0.f, 0.f, 0.f);
    if (t > 0) xs = ((const float4*)x)[i - C4];

    float4 mk = ((const float4*)tmk)[c4];
    float4 mv = ((const float4*)tmv)[c4];
    float4 mr = ((const float4*)tmr)[c4];

    float kx = xc.x * mk.x + xs.x * (1.f - mk.x);
    float ky = xc.y * mk.y + xs.y * (1.f - mk.y);
    float kz = xc.z * mk.z + xs.z * (1.f - mk.z);
    float kw = xc.w * mk.w + xs.w * (1.f - mk.w);
    float vx = xc.x * mv.x + xs.x * (1.f - mv.x);
    float vy = xc.y * mv.y + xs.y * (1.f - mv.y);
    float vz = xc.z * mv.z + xs.z * (1.f - mv.z);
    float vw = xc.w * mv.w + xs.w * (1.f - mv.w);
    float rx = xc.x * mr.x + xs.x * (1.f - mr.x);
    float ry = xc.y * mr.y + xs.y * (1.f - mr.y);
    float rz = xc.z * mr.z + xs.z * (1.f - mr.z);
    float rw = xc.w * mr.w + xs.w * (1.f - mr.w);

    ((uint2*)g_xk)[i] = make_uint2(pack_h2(kx, ky), pack_h2(kz, kw));
    ((uint2*)g_xv)[i] = make_uint2(pack_h2(vx, vy), pack_h2(vz, vw));
    ((uint2*)g_xr)[i] = make_uint2(pack_h2(rx, ry), pack_h2(rz, rw));
}

// ---------------- fp16 mma.sync GEMM (128x256 tile, 256 threads) ---------------
// C[m,n] = sum_k A[m,k]*W[n,k]; fp16 in, OT out. CTA 128x256, BK=64,
// 4-stage cp.async, one __syncthreads per k-iter. 8 warps of 64x64 (2m x 4n).
// Register budget: ~238/thread * 256 = 61k < 64k RF — no spill, 1 CTA/SM.
#define GBM 128
#define GBN 256
#define STG 49152                 // per-stage bytes: A 16K + W 32K
#define GSMEM (4 * STG)           // 192 KB

template <typename OT>
__global__ __launch_bounds__(256, 1)
void gemm_f16(const __half* __restrict__ A0, const __half* __restrict__ W0,
              OT* __restrict__ C0,
              const __half* __restrict__ A1, const __half* __restrict__ W1,
              OT* __restrict__ C1,
              const __half* __restrict__ A2, const __half* __restrict__ W2,
              OT* __restrict__ C2) {
    extern __shared__ char smem[];
    u32 sb = smem_u32(smem);
    const int tid = threadIdx.x, lane = tid & 31, wid = tid >> 5;
    const int bm = blockIdx.y * GBM, bn = blockIdx.x * GBN;
    const int mband = (wid >> 2) * 64, nband = (wid & 3) * 64;

    const __half* A = (blockIdx.z == 0) ? A0 : (blockIdx.z == 1) ? A1 : A2;
    const __half* W = (blockIdx.z == 0) ? W0 : (blockIdx.z == 1) ? W1 : W2;
    OT*           C = (blockIdx.z == 0) ? C0 : (blockIdx.z == 1) ? C1 : C2;

    const int arow = lane & 15;
    const int acg  = (lane >> 4) * 16;
    const int brow = ((lane >> 4) & 1) * 8 + (lane & 7);
    const int bcg  = ((lane >> 3) & 1) * 16;

    float acc[4][8][4];
#pragma unroll
    for (int i = 0; i < 4; i++)
#pragma unroll
        for (int j = 0; j < 8; j++)
#pragma unroll
            for (int q = 0; q < 4; q++) acc[i][j][q] = 0.f;

    const __half* Ag = A + (size_t)bm * D_C;
    const __half* Wg = W + (size_t)bn * D_C;

    // stage kt -> smem buffer (kt%4): A 128x64h at +0, W 256x64h at +16384
#define ISSUE(kt)                                                              \
    {                                                                          \
        u32 st = sb + ((kt) & 3) * STG;                                        \
        int koff = (kt) * 64;                                                  \
        _Pragma("unroll")                                                      \
        for (int ii = 0; ii < 4; ii++) {                                       \
            int g = tid + (ii << 8);                                           \
            int row = g >> 3, c8 = g & 7;                                      \
            u32 so = SWZ(row * 128 + c8 * 16);                                 \
            cpasync16(st + so, Ag + (size_t)row * D_C + koff + c8 * 8);        \
        }                                                                      \
        _Pragma("unroll")                                                      \
        for (int ii = 0; ii < 8; ii++) {                                       \
            int g = tid + (ii << 8);                                           \
            int row = g >> 3, c8 = g & 7;                                      \
            u32 so = SWZ(row * 128 + c8 * 16);                                 \
            cpasync16(st + 16384 + so, Wg + (size_t)row * D_C + koff + c8 * 8);\
        }                                                                      \
        CP_COMMIT;                                                             \
    }

    ISSUE(0); ISSUE(1); ISSUE(2);
    for (int kt = 0; kt < 16; kt++) {
        if (kt < 14)       { CP_WAIT2; }
        else if (kt == 14) { CP_WAIT1; }
        else               { CP_WAIT0; }
        __syncthreads();
        if (kt + 3 < 16) ISSUE(kt + 3);

        u32 aB = sb + (kt & 3) * STG;
        u32 bB = aB + 16384;
#pragma unroll
        for (int s = 0; s < 4; s++) {
            u32 af[4][4];
#pragma unroll
            for (int i = 0; i < 4; i++) {
                u32 addr = aB + SWZ((mband + 16 * i + arow) * 128 + s * 32 + acg);
                ldsm4(af[i][0], af[i][1], af[i][2], af[i][3], addr);
            }
#pragma unroll
            for (int jp = 0; jp < 4; jp++) {
                u32 b0, b1, b2, b3;
                u32 addr = bB + SWZ((nband + 16 * jp + brow) * 128 + s * 32 + bcg);
                ldsm4(b0, b1, b2, b3, addr);
#pragma unroll
                for (int i = 0; i < 4; i++) {
                    mma_f16(acc[i][2 * jp],     af[i][0], af[i][1], af[i][2], af[i][3], b0, b1);
                    mma_f16(acc[i][2 * jp + 1], af[i][0], af[i][1], af[i][2], af[i][3], b2, b3);
                }
            }
        }
    }

#pragma unroll
    for (int i = 0; i < 4; i++) {
        int row = bm + mband + 16 * i + (lane >> 2);
#pragma unroll
        for (int j = 0; j < 8; j++) {
            int col = bn + nband + 8 * j + 2 * (lane & 3);
            st2(C, (size_t)row * D_C + col,       acc[i][j][0], acc[i][j][1]);
            st2(C, (size_t)(row + 8) * D_C + col, acc[i][j][2], acc[i][j][3]);
        }
    }
}

// ---------------- WKV chunked scan (fp16 k/v/r IO) ----------------------------
// pass1: per (chain, chunk) compute chunk-local state from zero init.
__global__ void wkv_pass1(const float* __restrict__ w) {
    int g = blockIdx.x * blockDim.x + threadIdx.x;  // 0..SCH*NCH-1
    int chain = g & (NCH - 1), s = g >> 13;
    int b = chain >> 10, c = chain & (D_C - 1);
    float wn = -__expf(w[c]);

    size_t base = (size_t)b * N_T * D_C + (size_t)s * LCH * D_C + c;
    const __half* kp = g_k + base;
    const __half* vp = g_v + base;

    float aa = 0.f, bb = 0.f, pp = -1e38f;
#pragma unroll 8
    for (int j = 0; j < LCH; j++) {
        float kt = __half2float(kp[(size_t)j * D_C]);
        float vt = __half2float(vp[(size_t)j * D_C]);
        float ww2 = pp + wn;
        float p2  = fmaxf(ww2, kt);
        float e1b = __expf(ww2 - p2);
        float e2b = __expf(kt - p2);
        aa = e1b * aa + e2b * vt;
        bb = e1b * bb + e2b;
        pp = p2;
    }
    int o = s * NCH + chain;
    g_saa[o] = aa; g_sbb[o] = bb; g_spp[o] = pp;
}

// pass2: sequential merge over chunks; store incoming state per chunk.
__global__ void wkv_pass2(const float* __restrict__ w) {
    int chain = blockIdx.x * blockDim.x + threadIdx.x;  // 0..NCH-1
    int c = chain & (D_C - 1);
    float wn = -__expf(w[c]);
    float Lwn = (float)LCH * wn;

    float aa = 0.f, bb = 0.f, pp = -1e38f;
#pragma unroll
    for (int s = 0; s < SCH; s++) {
        int o = s * NCH + chain;
        g_iaa[o] = aa; g_ibb[o] = bb; g_ipp[o] = pp;
        float la = g_saa[o], lb = g_sbb[o], lp = g_spp[o];
        float ppa = pp + Lwn;
        float ppm = fmaxf(ppa, lp);
        float e1 = __expf(ppa - ppm);
        float e2 = __expf(lp - ppm);
        aa = e1 * aa + e2 * la;
        bb = e1 * bb + e2 * lb;
        pp = ppm;
    }
}

// pass3: replay each chunk from incoming state, produce gated outputs.
__global__ void wkv_pass3(const float* __restrict__ w,
                          const float* __restrict__ u) {
    int g = blockIdx.x * blockDim.x + threadIdx.x;
    int chain = g & (NCH - 1), s = g >> 13;
    int b = chain >> 10, c = chain & (D_C - 1);
    float wn = -__expf(w[c]);
    float uc = u[c];

    int o = s * NCH + chain;
    float aa = g_iaa[o], bb = g_ibb[o], pp = g_ipp[o];

    size_t base = (size_t)b * N_T * D_C + (size_t)s * LCH * D_C + c;
    const __half* kp = g_k + base;
    const __half* vp = g_v + base;
    const __half* rp = g_r + base;
    __half*       op = g_rw + base;

#pragma unroll 8
    for (int j = 0; j < LCH; j++) {
        float kt = __half2float(kp[(size_t)j * D_C]);
        float vt = __half2float(vp[(size_t)j * D_C]);
        float rt = __half2float(rp[(size_t)j * D_C]);

        float ww = uc + kt;
        float p  = fmaxf(pp, ww);
        float e1 = __expf(pp - p);
        float e2 = __expf(ww - p);
        float y  = __fdividef(e1 * aa + e2 * vt, e1 * bb + e2);

        float sg = __fdividef(1.f, 1.f + __expf(-rt));
        op[(size_t)j * D_C] = __float2half_rn(y * sg);

        float ww2 = pp + wn;
        float p2  = fmaxf(ww2, kt);
        float e1b = __expf(ww2 - p2);
        float e2b = __expf(kt - p2);
        aa = e1b * aa + e2b * vt;
        bb = e1b * bb + e2b;
        pp = p2;
    }
}

// ---------------- launch (single stream — graph-capture safe) -----------------
extern "C" void kernel_launch(void* const* d_in, const int* in_sizes, int n_in,
                              void* d_out, int out_size) {
    const float* x   = (const float*)d_in[0];
    const float* w   = (const float*)d_in[1];
    const float* u   = (const float*)d_in[2];
    const float* tmk = (const float*)d_in[3];
    const float* tmv = (const float*)d_in[4];
    const float* tmr = (const float*)d_in[5];
    const float* Wk  = (const float*)d_in[6];
    const float* Wv  = (const float*)d_in[7];
    const float* Wr  = (const float*)d_in[8];
    const float* Wo  = (const float*)d_in[9];
    float* out = (float*)d_out;

    __half *xk, *xv, *xr, *rw, *wk, *wv, *wr, *wo, *k, *v, *r;
    cudaGetSymbolAddress((void**)&xk, g_xk);
    cudaGetSymbolAddress((void**)&xv, g_xv);
    cudaGetSymbolAddress((void**)&xr, g_xr);
    cudaGetSymbolAddress((void**)&rw, g_rw);
    cudaGetSymbolAddress((void**)&wk, g_wk);
    cudaGetSymbolAddress((void**)&wv, g_wv);
    cudaGetSymbolAddress((void**)&wr, g_wr);
    cudaGetSymbolAddress((void**)&wo, g_wo);
    cudaGetSymbolAddress((void**)&k,  g_k);
    cudaGetSymbolAddress((void**)&v,  g_v);
    cudaGetSymbolAddress((void**)&r,  g_r);

    cudaFuncSetAttribute(gemm_f16<__half>,
                         cudaFuncAttributeMaxDynamicSharedMemorySize, GSMEM);
    cudaFuncSetAttribute(gemm_f16<float>,
                         cudaFuncAttributeMaxDynamicSharedMemorySize, GSMEM);

    // 1) fp16 weights + mixed activations
    wconv_kernel<<<dim3(1024, 4), 256>>>((const float4*)Wk, wk,
                                         (const float4*)Wv, wv,
                                         (const float4*)Wr, wr,
                                         (const float4*)Wo, wo);
    mix_kernel<<<(M_TOT * D_C / 4) / 256, 256>>>(x, tmk, tmv, tmr);

    // 2) K/V/R projections in ONE z-batched launch (fp16 out)
    dim3 gg3(D_C / GBN, M_TOT / GBM, 3);   // (4, 128, 3)
    gemm_f16<__half><<<gg3, 256, GSMEM>>>(xk, wk, k, xv, wv, v, xr, wr, r);

    // 3) WKV chunked scan (parallel over SCH chunks) + sigmoid gate
    wkv_pass1<<<(SCH * NCH) / 256, 256>>>(w);
    wkv_pass2<<<NCH / 256, 256>>>(w);
    wkv_pass3<<<(SCH * NCH) / 256, 256>>>(w, u);

    // 4) output projection (fp32 out to d_out)
    dim3 gg1(D_C / GBN, M_TOT / GBM, 1);   // (4, 128, 1)
    gemm_f16<float><<<gg1, 256, GSMEM>>>(rw, wo, out, rw, wo, out, rw, wo, out);
}

// round 16
// speedup vs baseline: 3.0411x; 1.0595x over previous
#include <cuda_runtime.h>
#include <cuda_fp16.h>
#include <stdint.h>

typedef unsigned int u32;
typedef unsigned long long u64;

#define D_C   1024
#define N_T   2048
#define M_TOT 16384   // 8 * 2048
#define NCH   8192    // B * D_C chains
#define SCH   32      // scan chunks
#define LCH   64      // tokens per chunk (SCH*LCH = N_T)

// ---------------- scratch (__device__ globals; no cudaMalloc allowed) ---------
__device__ __half g_xk[(size_t)M_TOT * D_C];
__device__ __half g_xv[(size_t)M_TOT * D_C];
__device__ __half g_xr[(size_t)M_TOT * D_C];
__device__ __half g_rw[(size_t)M_TOT * D_C];
__device__ __half g_k [(size_t)M_TOT * D_C];
__device__ __half g_v [(size_t)M_TOT * D_C];
__device__ __half g_r [(size_t)M_TOT * D_C];
__device__ __half g_wk[(size_t)D_C * D_C];
__device__ __half g_wv[(size_t)D_C * D_C];
__device__ __half g_wr[(size_t)D_C * D_C];
__device__ __half g_wo[(size_t)D_C * D_C];
// chunked-scan state: [SCH][NCH]
__device__ float g_saa[SCH * NCH], g_sbb[SCH * NCH], g_spp[SCH * NCH];
__device__ float g_iaa[SCH * NCH], g_ibb[SCH * NCH], g_ipp[SCH * NCH];

// ---------------- PTX helpers (baseline ISA only) ------------------------------
__device__ __forceinline__ u32 smem_u32(const void* p) {
    u32 a;
    asm("{ .reg .u64 t; cvta.to.shared.u64 t, %1; cvt.u32.u64 %0, t; }"
        : "=r"(a) : "l"(p));
    return a;
}
#define SWZ(o) ((u32)(o) ^ ((((u32)(o)) >> 3) & 0x70))

__device__ __forceinline__ void cpasync16(u32 s, const void* g) {
    asm volatile("cp.async.cg.shared.global [%0], [%1], 16;" :: "r"(s), "l"(g));
}
#define CP_COMMIT asm volatile("cp.async.commit_group;" ::: "memory")
#define CP_WAIT1  asm volatile("cp.async.wait_group 1;" ::: "memory")
#define CP_WAIT0  asm volatile("cp.async.wait_group 0;" ::: "memory")

__device__ __forceinline__ void ldsm4(u32& r0, u32& r1, u32& r2, u32& r3, u32 a) {
    asm volatile("ldmatrix.sync.aligned.m8n8.x4.shared.b16 {%0,%1,%2,%3}, [%4];"
                 : "=r"(r0), "=r"(r1), "=r"(r2), "=r"(r3) : "r"(a));
}

__device__ __forceinline__ void mma_f16(float* d, u32 a0, u32 a1, u32 a2, u32 a3,
                                        u32 b0, u32 b1) {
    asm volatile(
        "mma.sync.aligned.m16n8k16.row.col.f32.f16.f16.f32 "
        "{%0,%1,%2,%3},{%4,%5,%6,%7},{%8,%9},{%0,%1,%2,%3};"
        : "+f"(d[0]), "+f"(d[1]), "+f"(d[2]), "+f"(d[3])
        : "r"(a0), "r"(a1), "r"(a2), "r"(a3), "r"(b0), "r"(b1));
}

__device__ __forceinline__ u32 pack_h2(float lo, float hi) {
    __half2 h = __floats2half2_rn(lo, hi);
    return *(u32*)&h;
}

// epilogue store: fp32 or fp16 output, same call site
__device__ __forceinline__ void st2(float* C, size_t idx, float a, float b) {
    *(float2*)&C[idx] = make_float2(a, b);
}
__device__ __forceinline__ void st2(__half* C, size_t idx, float a, float b) {
    *(__half2*)&C[idx] = __floats2half2_rn(a, b);
}

// ---------------- weight convert: 4 matrices fp32 -> fp16, one launch ---------
__global__ void wconv_kernel(const float4* __restrict__ W0, __half* __restrict__ O0,
                             const float4* __restrict__ W1, __half* __restrict__ O1,
                             const float4* __restrict__ W2, __half* __restrict__ O2,
                             const float4* __restrict__ W3, __half* __restrict__ O3) {
    int i = blockIdx.x * blockDim.x + threadIdx.x;
    const float4* W = (blockIdx.y == 0) ? W0 : (blockIdx.y == 1) ? W1
                    : (blockIdx.y == 2) ? W2 : W3;
    __half* O = (blockIdx.y == 0) ? O0 : (blockIdx.y == 1) ? O1
              : (blockIdx.y == 2) ? O2 : O3;
    float4 v = W[i];
    ((uint2*)O)[i] = make_uint2(pack_h2(v.x, v.y), pack_h2(v.z, v.w));
}

// ---------------- token-shift mix -> fp16 -------------------------------------
__global__ void mix_kernel(const float* __restrict__ x,
                           const float* __restrict__ tmk,
                           const float* __restrict__ tmv,
                           const float* __restrict__ tmr) {
    const int C4 = D_C / 4;
    int i = blockIdx.x * blockDim.x + threadIdx.x;
    int c4 = i & (C4 - 1);
    int bt = i >> 8;
    int t  = bt & (N_T - 1);

    float4 xc = ((const float4*)x)[i];
    float4 xs = make_float4(0.f, 0.f, 0.f, 0.f);
    if (t > 0) xs = ((const float4*)x)[i - C4];

    float4 mk = ((const float4*)tmk)[c4];
    float4 mv = ((const float4*)tmv)[c4];
    float4 mr = ((const float4*)tmr)[c4];

    float kx = xc.x * mk.x + xs.x * (1.f - mk.x);
    float ky = xc.y * mk.y + xs.y * (1.f - mk.y);
    float kz = xc.z * mk.z + xs.z * (1.f - mk.z);
    float kw = xc.w * mk.w + xs.w * (1.f - mk.w);
    float vx = xc.x * mv.x + xs.x * (1.f - mv.x);
    float vy = xc.y * mv.y + xs.y * (1.f - mv.y);
    float vz = xc.z * mv.z + xs.z * (1.f - mv.z);
    float vw = xc.w * mv.w + xs.w * (1.f - mv.w);
    float rx = xc.x * mr.x + xs.x * (1.f - mr.x);
    float ry = xc.y * mr.y + xs.y * (1.f - mr.y);
    float rz = xc.z * mr.z + xs.z * (1.f - mr.z);
    float rw = xc.w * mr.w + xs.w * (1.f - mr.w);

    ((uint2*)g_xk)[i] = make_uint2(pack_h2(kx, ky), pack_h2(kz, kw));
    ((uint2*)g_xv)[i] = make_uint2(pack_h2(vx, vy), pack_h2(vz, vw));
    ((uint2*)g_xr)[i] = make_uint2(pack_h2(rx, ry), pack_h2(rz, rw));
}

// ---------------- fp16 mma.sync GEMM (128x128 tile, 8 warps of 64x32) ----------
// C[m,n] = sum_k A[m,k]*W[n,k]; fp16 in, OT out. CTA 128x128, BK=64,
// 3-stage cp.async, one __syncthreads per k-iter, 2 CTAs/SM -> 16 warps/SM.
// Warp tile 64x32 (acc 64 fp32 regs; ~110 regs/thread -> no spill at occ 2).
#define GBM 128
#define GBN 128
#define STG 32768                 // per-stage bytes: A 16K + B 16K
#define GSMEM (3 * STG)           // 96 KB

template <typename OT>
__global__ __launch_bounds__(256, 2)
void gemm_f16(const __half* __restrict__ A0, const __half* __restrict__ W0,
              OT* __restrict__ C0,
              const __half* __restrict__ A1, const __half* __restrict__ W1,
              OT* __restrict__ C1,
              const __half* __restrict__ A2, const __half* __restrict__ W2,
              OT* __restrict__ C2) {
    extern __shared__ char smem[];
    u32 sb = smem_u32(smem);
    const int tid = threadIdx.x, lane = tid & 31, wid = tid >> 5;
    const int bm = blockIdx.y * GBM, bn = blockIdx.x * GBN;
    const int mband = (wid >> 2) * 64;     // 2 m-bands of 64
    const int nband = (wid & 3) * 32;      // 4 n-bands of 32

    const __half* A = (blockIdx.z == 0) ? A0 : (blockIdx.z == 1) ? A1 : A2;
    const __half* W = (blockIdx.z == 0) ? W0 : (blockIdx.z == 1) ? W1 : W2;
    OT*           C = (blockIdx.z == 0) ? C0 : (blockIdx.z == 1) ? C1 : C2;

    const int arow = lane & 15;
    const int acg  = (lane >> 4) * 16;
    const int brow = ((lane >> 4) & 1) * 8 + (lane & 7);
    const int bcg  = ((lane >> 3) & 1) * 16;

    float acc[4][4][4];                    // 4 m-tiles x 4 n8-tiles x 4
#pragma unroll
    for (int i = 0; i < 4; i++)
#pragma unroll
        for (int j = 0; j < 4; j++)
#pragma unroll
            for (int q = 0; q < 4; q++) acc[i][j][q] = 0.f;

    const __half* Ag = A + (size_t)bm * D_C;
    const __half* Wg = W + (size_t)bn * D_C;

    // stage kt -> smem buffer (kt%3): A 128x64h at +0, B 128x64h at +16384
    // 256 threads: 4 A lines + 4 B lines each (16B granularity)
#define ISSUE(kt)                                                              \
    {                                                                          \
        u32 st = sb + ((kt) % 3) * STG;                                        \
        int koff = (kt) * 64;                                                  \
        _Pragma("unroll")                                                      \
        for (int ii = 0; ii < 4; ii++) {                                       \
            int g = tid + (ii << 8);                                           \
            int row = g >> 3, c8 = g & 7;                                      \
            u32 so = SWZ(row * 128 + c8 * 16);                                 \
            cpasync16(st + so,         Ag + (size_t)row * D_C + koff + c8 * 8);\
            cpasync16(st + 16384 + so, Wg + (size_t)row * D_C + koff + c8 * 8);\
        }                                                                      \
        CP_COMMIT;                                                             \
    }

    ISSUE(0); ISSUE(1);
    for (int kt = 0; kt < 16; kt++) {
        if (kt == 15) { CP_WAIT0; } else { CP_WAIT1; }
        __syncthreads();
        if (kt + 2 < 16) ISSUE(kt + 2);

        u32 aB = sb + (kt % 3) * STG;
        u32 bB = aB + 16384;
#pragma unroll
        for (int s = 0; s < 4; s++) {              // 4 k-steps of 16
            u32 af[4][4];
#pragma unroll
            for (int i = 0; i < 4; i++) {
                u32 addr = aB + SWZ((mband + 16 * i + arow) * 128 + s * 32 + acg);
                ldsm4(af[i][0], af[i][1], af[i][2], af[i][3], addr);
            }
#pragma unroll
            for (int jp = 0; jp < 2; jp++) {       // 2 n16 groups (32 cols)
                u32 b0, b1, b2, b3;
                u32 addr = bB + SWZ((nband + 16 * jp + brow) * 128 + s * 32 + bcg);
                ldsm4(b0, b1, b2, b3, addr);
#pragma unroll
                for (int i = 0; i < 4; i++) {
                    mma_f16(acc[i][2 * jp],     af[i][0], af[i][1], af[i][2], af[i][3], b0, b1);
                    mma_f16(acc[i][2 * jp + 1], af[i][0], af[i][1], af[i][2], af[i][3], b2, b3);
                }
            }
        }
    }

#pragma unroll
    for (int i = 0; i < 4; i++) {
        int row = bm + mband + 16 * i + (lane >> 2);
#pragma unroll
        for (int j = 0; j < 4; j++) {
            int col = bn + nband + 8 * j + 2 * (lane & 3);
            st2(C, (size_t)row * D_C + col,       acc[i][j][0], acc[i][j][1]);
            st2(C, (size_t)(row + 8) * D_C + col, acc[i][j][2], acc[i][j][3]);
        }
    }
}

// ---------------- WKV chunked scan (fp16 k/v/r IO) ----------------------------
// pass1: per (chain, chunk) compute chunk-local state from zero init.
__global__ void wkv_pass1(const float* __restrict__ w) {
    int g = blockIdx.x * blockDim.x + threadIdx.x;  // 0..SCH*NCH-1
    int chain = g & (NCH - 1), s = g >> 13;
    int b = chain >> 10, c = chain & (D_C - 1);
    float wn = -__expf(w[c]);

    size_t base = (size_t)b * N_T * D_C + (size_t)s * LCH * D_C + c;
    const __half* kp = g_k + base;
    const __half* vp = g_v + base;

    float aa = 0.f, bb = 0.f, pp = -1e38f;
#pragma unroll 8
    for (int j = 0; j < LCH; j++) {
        float kt = __half2float(kp[(size_t)j * D_C]);
        float vt = __half2float(vp[(size_t)j * D_C]);
        float ww2 = pp + wn;
        float p2  = fmaxf(ww2, kt);
        float e1b = __expf(ww2 - p2);
        float e2b = __expf(kt - p2);
        aa = e1b * aa + e2b * vt;
        bb = e1b * bb + e2b;
        pp = p2;
    }
    int o = s * NCH + chain;
    g_saa[o] = aa; g_sbb[o] = bb; g_spp[o] = pp;
}

// pass2: sequential merge over chunks; store incoming state per chunk.
__global__ void wkv_pass2(const float* __restrict__ w) {
    int chain = blockIdx.x * blockDim.x + threadIdx.x;  // 0..NCH-1
    int c = chain & (D_C - 1);
    float wn = -__expf(w[c]);
    float Lwn = (float)LCH * wn;

    float aa = 0.f, bb = 0.f, pp = -1e38f;
#pragma unroll
    for (int s = 0; s < SCH; s++) {
        int o = s * NCH + chain;
        g_iaa[o] = aa; g_ibb[o] = bb; g_ipp[o] = pp;
        float la = g_saa[o], lb = g_sbb[o], lp = g_spp[o];
        float ppa = pp + Lwn;
        float ppm = fmaxf(ppa, lp);
        float e1 = __expf(ppa - ppm);
        float e2 = __expf(lp - ppm);
        aa = e1 * aa + e2 * la;
        bb = e1 * bb + e2 * lb;
        pp = ppm;
    }
}

// pass3: replay each chunk from incoming state, produce gated outputs.
__global__ void wkv_pass3(const float* __restrict__ w,
                          const float* __restrict__ u) {
    int g = blockIdx.x * blockDim.x + threadIdx.x;
    int chain = g & (NCH - 1), s = g >> 13;
    int b = chain >> 10, c = chain & (D_C - 1);
    float wn = -__expf(w[c]);
    float uc = u[c];

    int o = s * NCH + chain;
    float aa = g_iaa[o], bb = g_ibb[o], pp = g_ipp[o];

    size_t base = (size_t)b * N_T * D_C + (size_t)s * LCH * D_C + c;
    const __half* kp = g_k + base;
    const __half* vp = g_v + base;
    const __half* rp = g_r + base;
    __half*       op = g_rw + base;

#pragma unroll 8
    for (int j = 0; j < LCH; j++) {
        float kt = __half2float(kp[(size_t)j * D_C]);
        float vt = __half2float(vp[(size_t)j * D_C]);
        float rt = __half2float(rp[(size_t)j * D_C]);

        float ww = uc + kt;
        float p  = fmaxf(pp, ww);
        float e1 = __expf(pp - p);
        float e2 = __expf(ww - p);
        float y  = __fdividef(e1 * aa + e2 * vt, e1 * bb + e2);

        float sg = __fdividef(1.f, 1.f + __expf(-rt));
        op[(size_t)j * D_C] = __float2half_rn(y * sg);

        float ww2 = pp + wn;
        float p2  = fmaxf(ww2, kt);
        float e1b = __expf(ww2 - p2);
        float e2b = __expf(kt - p2);
        aa = e1b * aa + e2b * vt;
        bb = e1b * bb + e2b;
        pp = p2;
    }
}

// ---------------- launch (single stream — graph-capture safe) -----------------
extern "C" void kernel_launch(void* const* d_in, const int* in_sizes, int n_in,
                              void* d_out, int out_size) {
    const float* x   = (const float*)d_in[0];
    const float* w   = (const float*)d_in[1];
    const float* u   = (const float*)d_in[2];
    const float* tmk = (const float*)d_in[3];
    const float* tmv = (const float*)d_in[4];
    const float* tmr = (const float*)d_in[5];
    const float* Wk  = (const float*)d_in[6];
    const float* Wv  = (const float*)d_in[7];
    const float* Wr  = (const float*)d_in[8];
    const float* Wo  = (const float*)d_in[9];
    float* out = (float*)d_out;

    __half *xk, *xv, *xr, *rw, *wk, *wv, *wr, *wo, *k, *v, *r;
    cudaGetSymbolAddress((void**)&xk, g_xk);
    cudaGetSymbolAddress((void**)&xv, g_xv);
    cudaGetSymbolAddress((void**)&xr, g_xr);
    cudaGetSymbolAddress((void**)&rw, g_rw);
    cudaGetSymbolAddress((void**)&wk, g_wk);
    cudaGetSymbolAddress((void**)&wv, g_wv);
    cudaGetSymbolAddress((void**)&wr, g_wr);
    cudaGetSymbolAddress((void**)&wo, g_wo);
    cudaGetSymbolAddress((void**)&k,  g_k);
    cudaGetSymbolAddress((void**)&v,  g_v);
    cudaGetSymbolAddress((void**)&r,  g_r);

    cudaFuncSetAttribute(gemm_f16<__half>,
                         cudaFuncAttributeMaxDynamicSharedMemorySize, GSMEM);
    cudaFuncSetAttribute(gemm_f16<float>,
                         cudaFuncAttributeMaxDynamicSharedMemorySize, GSMEM);

    // 1) fp16 weights + mixed activations
    wconv_kernel<<<dim3(1024, 4), 256>>>((const float4*)Wk, wk,
                                         (const float4*)Wv, wv,
                                         (const float4*)Wr, wr,
                                         (const float4*)Wo, wo);
    mix_kernel<<<(M_TOT * D_C / 4) / 256, 256>>>(x, tmk, tmv, tmr);

    // 2) K/V/R projections in ONE z-batched launch (fp16 out)
    dim3 gg3(D_C / GBN, M_TOT / GBM, 3);   // (8, 128, 3)
    gemm_f16<__half><<<gg3, 256, GSMEM>>>(xk, wk, k, xv, wv, v, xr, wr, r);

    // 3) WKV chunked scan (parallel over SCH chunks) + sigmoid gate
    wkv_pass1<<<(SCH * NCH) / 256, 256>>>(w);
    wkv_pass2<<<NCH / 256, 256>>>(w);
    wkv_pass3<<<(SCH * NCH) / 256, 256>>>(w, u);

    // 4) output projection (fp32 out to d_out)
    dim3 gg1(D_C / GBN, M_TOT / GBM, 1);   // (8, 128, 1)
    gemm_f16<float><<<gg1, 256, GSMEM>>>(rw, wo, out, rw, wo, out, rw, wo, out);
}